// round 4
// baseline (speedup 1.0000x reference)
#include <cuda_runtime.h>
#include <stdint.h>

typedef unsigned long long u64;

// ---- packed fp32x2 primitives (SASS FFMA2 path, 2x fp32 throughput) ----
__device__ __forceinline__ u64 fma2(u64 a, u64 b, u64 c) {
    u64 d; asm("fma.rn.f32x2 %0, %1, %2, %3;" : "=l"(d) : "l"(a), "l"(b), "l"(c)); return d;
}
__device__ __forceinline__ u64 mul2(u64 a, u64 b) {
    u64 d; asm("mul.rn.f32x2 %0, %1, %2;" : "=l"(d) : "l"(a), "l"(b)); return d;
}
__device__ __forceinline__ u64 pack2(float lo, float hi) {
    u64 d; asm("mov.b64 %0, {%1, %2};" : "=l"(d) : "f"(lo), "f"(hi)); return d;
}
__device__ __forceinline__ void unpack2(u64 v, float& lo, float& hi) {
    asm("mov.b64 {%0, %1}, %2;" : "=f"(lo), "=f"(hi) : "l"(v));
}

// leaky(x) = max(x, 0.01x)  (exact elementwise for slope<1)
__device__ __forceinline__ u64 leaky2(u64 x) {
    const u64 SL = 0x3C23D70A3C23D70AULL;  // (0.01f, 0.01f)
    u64 s = mul2(x, SL);
    float xl, xh, sl, sh;
    unpack2(x, xl, xh); unpack2(s, sl, sh);
    return pack2(fmaxf(xl, sl), fmaxf(xh, sh));
}

struct Params { const float* p[20]; };  // [0..4]=ws_logs [5..9]=bs_logs [10..14]=ws_b [15..19]=bs_b

// One 8->8 layer on TWO packed row-pairs; weights via 16B LDS of duplicated pairs.
__device__ __forceinline__ void layer2pairQ(
    const ulonglong2* __restrict__ W, const u64* __restrict__ B,
    const u64* in0, const u64* in1, u64* out0, u64* out1, bool act)
{
#pragma unroll
    for (int j = 0; j < 8; j++) {
        u64 a0 = B[j], a1 = B[j];
#pragma unroll
        for (int i2 = 0; i2 < 4; i2++) {
            ulonglong2 w = W[j * 4 + i2];          // LDS.128: (w2i,w2i),(w2i+1,w2i+1)
            a0 = fma2(w.x, in0[2 * i2], a0);
            a1 = fma2(w.x, in1[2 * i2], a1);
            a0 = fma2(w.y, in0[2 * i2 + 1], a0);
            a1 = fma2(w.y, in1[2 * i2 + 1], a1);
        }
        out0[j] = act ? leaky2(a0) : a0;
        out1[j] = act ? leaky2(a1) : a1;
    }
}

template <int IOW>
__device__ __forceinline__ float4 ld4(const float* p) {
    if (IOW == 4) return *(const float4*)p;
    else if (IOW == 2) { float2 u = *(const float2*)p, v = *(const float2*)(p + 2);
                         return make_float4(u.x, u.y, v.x, v.y); }
    else return make_float4(p[0], p[1], p[2], p[3]);
}
template <int IOW>
__device__ __forceinline__ void st4(float* p, float4 v) {
    if (IOW == 4) *(float4*)p = v;
    else if (IOW == 2) { *(float2*)p = make_float2(v.x, v.y);
                         *(float2*)(p + 2) = make_float2(v.z, v.w); }
    else { p[0] = v.x; p[1] = v.y; p[2] = v.z; p[3] = v.w; }
}

// IOW: I/O width in floats per memory op (4 = float4, 2 = float2, 1 = scalar)
template <int IOW>
__global__ __launch_bounds__(128, 5)
void affine_coupling_kernel(const float* __restrict__ z, float* __restrict__ out,
                            int batch, Params P)
{
    __shared__ ulonglong2 SWq[2][5][32];   // weights, duplicated pairs, 16B granules
    __shared__ u64 SB[2][5][8];            // biases, duplicated
    __shared__ ulonglong2 ZRs[8][128];     // per-thread zr stash (dense [j][tid])
    __shared__ ulonglong2 BUF[8][128];     // per-thread zl -> bv buffer

    const int tid = threadIdx.x;

    // weights: 320 ulonglong2
    for (int idx = tid; idx < 320; idx += 128) {
        int m = idx / 160, r = idx % 160, l = r / 32, k = r % 32;
        int j = k / 4, i2 = k % 4;
        const float* Wp = P.p[m * 10 + l];
        float w0 = Wp[j * 8 + i2 * 2], w1 = Wp[j * 8 + i2 * 2 + 1];
        SWq[m][l][k] = make_ulonglong2(pack2(w0, w0), pack2(w1, w1));
    }
    // biases: 80 u64
    for (int idx = tid; idx < 80; idx += 128) {
        int m = idx / 40, r = idx % 40, l = r / 8, k = r % 8;
        float v = P.p[m * 10 + 5 + l][k];
        SB[m][l][k] = pack2(v, v);
    }
    __syncthreads();

    const int lane = tid & 31;
    const int warp = tid >> 5;
    long long warpBase = ((long long)blockIdx.x * 4 + warp) * 128;
    if (warpBase >= batch) return;  // batch % 128 == 0 -> active warps are full

    // Each thread: 2 pairs = 4 rows. Pair p = (warpBase + 64p + lane, +32).
    int rA[2], rB[2];
    u64 zl[2][8];
#pragma unroll
    for (int p = 0; p < 2; p++) {
        rA[p] = (int)warpBase + p * 64 + lane;
        rB[p] = rA[p] + 32;
        const float* pa = z + (long long)rA[p] * 16;
        const float* pb = z + (long long)rB[p] * 16;
        float4 a0 = ld4<IOW>(pa),     a1 = ld4<IOW>(pa + 4);
        float4 a2 = ld4<IOW>(pa + 8), a3 = ld4<IOW>(pa + 12);
        float4 b0 = ld4<IOW>(pb),     b1 = ld4<IOW>(pb + 4);
        float4 b2 = ld4<IOW>(pb + 8), b3 = ld4<IOW>(pb + 12);

        // left-half passthrough: store immediately
        float* oa = out + (long long)rA[p] * 16;
        float* ob = out + (long long)rB[p] * 16;
        st4<IOW>(oa, a0);     st4<IOW>(oa + 4, a1);
        st4<IOW>(ob, b0);     st4<IOW>(ob + 4, b1);

        zl[p][0] = pack2(a0.x, b0.x); zl[p][1] = pack2(a0.y, b0.y);
        zl[p][2] = pack2(a0.z, b0.z); zl[p][3] = pack2(a0.w, b0.w);
        zl[p][4] = pack2(a1.x, b1.x); zl[p][5] = pack2(a1.y, b1.y);
        zl[p][6] = pack2(a1.z, b1.z); zl[p][7] = pack2(a1.w, b1.w);

        // zr -> smem stash (private slot, no sync needed)
        ZRs[p * 4 + 0][tid] = make_ulonglong2(pack2(a2.x, b2.x), pack2(a2.y, b2.y));
        ZRs[p * 4 + 1][tid] = make_ulonglong2(pack2(a2.z, b2.z), pack2(a2.w, b2.w));
        ZRs[p * 4 + 2][tid] = make_ulonglong2(pack2(a3.x, b3.x), pack2(a3.y, b3.y));
        ZRs[p * 4 + 3][tid] = make_ulonglong2(pack2(a3.z, b3.z), pack2(a3.w, b3.w));

        // zl -> buffer (will be restored for the log_s chain)
#pragma unroll
        for (int k2 = 0; k2 < 4; k2++)
            BUF[p * 4 + k2][tid] = make_ulonglong2(zl[p][2 * k2], zl[p][2 * k2 + 1]);
    }

    // ---- b chain (m=1), straight from register zl ----
    u64 s[2][8], t[2][8], bv[2][8];
    layer2pairQ(SWq[1][0], SB[1][0], zl[0], zl[1], s[0], s[1], true);   // zl dies here
    layer2pairQ(SWq[1][1], SB[1][1], s[0], s[1], t[0], t[1], true);
    layer2pairQ(SWq[1][2], SB[1][2], t[0], t[1], s[0], s[1], true);
    layer2pairQ(SWq[1][3], SB[1][3], s[0], s[1], t[0], t[1], true);
    layer2pairQ(SWq[1][4], SB[1][4], t[0], t[1], bv[0], bv[1], false);

    // restore zl from BUF, then overwrite BUF with bv
    u64 zl2[2][8];
#pragma unroll
    for (int p = 0; p < 2; p++)
#pragma unroll
        for (int k2 = 0; k2 < 4; k2++) {
            ulonglong2 v = BUF[p * 4 + k2][tid];
            zl2[p][2 * k2] = v.x; zl2[p][2 * k2 + 1] = v.y;
        }
#pragma unroll
    for (int p = 0; p < 2; p++)
#pragma unroll
        for (int k2 = 0; k2 < 4; k2++)
            BUF[p * 4 + k2][tid] = make_ulonglong2(bv[p][2 * k2], bv[p][2 * k2 + 1]);

    // ---- log_s chain (m=0) ----
    u64 ls[2][8];
    layer2pairQ(SWq[0][0], SB[0][0], zl2[0], zl2[1], s[0], s[1], true);
    layer2pairQ(SWq[0][1], SB[0][1], s[0], s[1], t[0], t[1], true);
    layer2pairQ(SWq[0][2], SB[0][2], t[0], t[1], s[0], s[1], true);
    layer2pairQ(SWq[0][3], SB[0][3], s[0], s[1], t[0], t[1], true);
    layer2pairQ(SWq[0][4], SB[0][4], t[0], t[1], ls[0], ls[1], false);

    // ---- epilogue: yr = exp(log_s) * zr + b ----
#pragma unroll
    for (int p = 0; p < 2; p++) {
        float yA[8], yB[8];
#pragma unroll
        for (int k2 = 0; k2 < 4; k2++) {
            ulonglong2 bq = BUF[p * 4 + k2][tid];
            ulonglong2 zq = ZRs[p * 4 + k2][tid];
            float lA0, lB0, lA1, lB1, bA0, bB0, bA1, bB1, zA0, zB0, zA1, zB1;
            unpack2(ls[p][2 * k2],     lA0, lB0);
            unpack2(ls[p][2 * k2 + 1], lA1, lB1);
            unpack2(bq.x, bA0, bB0);  unpack2(bq.y, bA1, bB1);
            unpack2(zq.x, zA0, zB0);  unpack2(zq.y, zA1, zB1);
            yA[2 * k2]     = fmaf(__expf(lA0), zA0, bA0);
            yB[2 * k2]     = fmaf(__expf(lB0), zB0, bB0);
            yA[2 * k2 + 1] = fmaf(__expf(lA1), zA1, bA1);
            yB[2 * k2 + 1] = fmaf(__expf(lB1), zB1, bB1);
        }
        float* oa = out + (long long)rA[p] * 16 + 8;
        float* ob = out + (long long)rB[p] * 16 + 8;
        st4<IOW>(oa,     make_float4(yA[0], yA[1], yA[2], yA[3]));
        st4<IOW>(oa + 4, make_float4(yA[4], yA[5], yA[6], yA[7]));
        st4<IOW>(ob,     make_float4(yB[0], yB[1], yB[2], yB[3]));
        st4<IOW>(ob + 4, make_float4(yB[4], yB[5], yB[6], yB[7]));
    }
}

extern "C" void kernel_launch(void* const* d_in, const int* in_sizes, int n_in,
                              void* d_out, int out_size)
{
    // ---- locate z: the (unique) huge input ----
    int zi = 0;
    for (int i = 0; i < n_in; i++) {
        if (in_sizes[i] > in_sizes[zi]) zi = i;
    }
    const float* z = (const float*)d_in[zi];
    long long batchLL = (long long)in_sizes[zi] / 16;
    int batch = (int)batchLL;
    float* out = (float*)d_out;

    // ---- build the 20 layer-parameter pointers, layout-adaptively ----
    Params P;
    if (n_in >= 21) {
        int k = 0;
        for (int i = 0; i < n_in && k < 20; i++) {
            if (i == zi) continue;
            P.p[k++] = (const float*)d_in[i];
        }
    } else {
        int wslot = 0, bslot = 0;  // 0 -> logs, 1 -> b
        for (int i = 0; i < n_in; i++) {
            if (i == zi) continue;
            const float* base = (const float*)d_in[i];
            int sz = in_sizes[i];
            if (sz == 320) {            // stacked weights (5,8,8)
                int m = (wslot++ == 0) ? 0 : 1;
                for (int l = 0; l < 5; l++) P.p[m * 10 + l] = base + 64 * l;
            } else if (sz == 40) {      // stacked biases (5,8)
                int m = (bslot++ == 0) ? 0 : 1;
                for (int l = 0; l < 5; l++) P.p[m * 10 + 5 + l] = base + 8 * l;
            }
        }
    }

    int rowsPerBlock = 512;                // 128 threads * 4 rows
    int grid = (int)((batchLL + rowsPerBlock - 1) / rowsPerBlock);

    uintptr_t mis = (uintptr_t)z | (uintptr_t)out;
    if ((mis & 15) == 0) {
        affine_coupling_kernel<4><<<grid, 128>>>(z, out, batch, P);
    } else if ((mis & 7) == 0) {
        affine_coupling_kernel<2><<<grid, 128>>>(z, out, batch, P);
    } else {
        affine_coupling_kernel<1><<<grid, 128>>>(z, out, batch, P);
    }
}

// round 5
// speedup vs baseline: 1.2866x; 1.2866x over previous
#include <cuda_runtime.h>
#include <stdint.h>

typedef unsigned long long u64;

// ---- packed fp32x2 primitives (SASS FFMA2 path, 2x fp32 throughput) ----
__device__ __forceinline__ u64 fma2(u64 a, u64 b, u64 c) {
    u64 d; asm("fma.rn.f32x2 %0, %1, %2, %3;" : "=l"(d) : "l"(a), "l"(b), "l"(c)); return d;
}
__device__ __forceinline__ u64 mul2(u64 a, u64 b) {
    u64 d; asm("mul.rn.f32x2 %0, %1, %2;" : "=l"(d) : "l"(a), "l"(b)); return d;
}
__device__ __forceinline__ u64 pack2(float lo, float hi) {
    u64 d; asm("mov.b64 %0, {%1, %2};" : "=l"(d) : "f"(lo), "f"(hi)); return d;
}
__device__ __forceinline__ void unpack2(u64 v, float& lo, float& hi) {
    asm("mov.b64 {%0, %1}, %2;" : "=f"(lo), "=f"(hi) : "l"(v));
}

// leaky(x) = max(x, 0.01x)  (exact elementwise for slope<1)
__device__ __forceinline__ u64 leaky2(u64 x) {
    const u64 SL = 0x3C23D70A3C23D70AULL;  // (0.01f, 0.01f)
    u64 s = mul2(x, SL);
    float xl, xh, sl, sh;
    unpack2(x, xl, xh); unpack2(s, sl, sh);
    return pack2(fmaxf(xl, sl), fmaxf(xh, sh));
}

struct Params { const float* p[20]; };  // [0..4]=ws_logs [5..9]=bs_logs [10..14]=ws_b [15..19]=bs_b

// One 8->8 layer on TWO packed row-pairs.
// Weights and biases read via broadcast LDS.128 (duplicated (w,w) pairs).
__device__ __forceinline__ void layer2pairQ(
    const ulonglong2* __restrict__ W, const ulonglong2* __restrict__ Bq,
    const u64* in0, const u64* in1, u64* out0, u64* out1, bool act)
{
#pragma unroll
    for (int j2 = 0; j2 < 4; j2++) {
        ulonglong2 bias = Bq[j2];               // biases for rows 2*j2, 2*j2+1
        u64 a0 = bias.x, a1 = bias.x;           // row j = 2*j2
        u64 c0 = bias.y, c1 = bias.y;           // row j = 2*j2+1
#pragma unroll
        for (int i2 = 0; i2 < 4; i2++) {
            ulonglong2 wa = W[(2 * j2)     * 4 + i2];   // LDS.128 broadcast
            ulonglong2 wc = W[(2 * j2 + 1) * 4 + i2];
            a0 = fma2(wa.x, in0[2 * i2],     a0);
            a1 = fma2(wa.x, in1[2 * i2],     a1);
            a0 = fma2(wa.y, in0[2 * i2 + 1], a0);
            a1 = fma2(wa.y, in1[2 * i2 + 1], a1);
            c0 = fma2(wc.x, in0[2 * i2],     c0);
            c1 = fma2(wc.x, in1[2 * i2],     c1);
            c0 = fma2(wc.y, in0[2 * i2 + 1], c0);
            c1 = fma2(wc.y, in1[2 * i2 + 1], c1);
        }
        out0[2 * j2]     = act ? leaky2(a0) : a0;
        out1[2 * j2]     = act ? leaky2(a1) : a1;
        out0[2 * j2 + 1] = act ? leaky2(c0) : c0;
        out1[2 * j2 + 1] = act ? leaky2(c1) : c1;
    }
}

template <int IOW>
__device__ __forceinline__ float4 ld4(const float* p) {
    if (IOW == 4) return *(const float4*)p;
    else if (IOW == 2) { float2 u = *(const float2*)p, v = *(const float2*)(p + 2);
                         return make_float4(u.x, u.y, v.x, v.y); }
    else return make_float4(p[0], p[1], p[2], p[3]);
}
template <int IOW>
__device__ __forceinline__ void st4(float* p, float4 v) {
    if (IOW == 4) *(float4*)p = v;
    else if (IOW == 2) { *(float2*)p = make_float2(v.x, v.y);
                         *(float2*)(p + 2) = make_float2(v.z, v.w); }
    else { p[0] = v.x; p[1] = v.y; p[2] = v.z; p[3] = v.w; }
}

// IOW: I/O width in floats per memory op (4 = float4, 2 = float2, 1 = scalar)
template <int IOW>
__global__ __launch_bounds__(128)
void affine_coupling_kernel(const float* __restrict__ z, float* __restrict__ out,
                            int batch, Params P)
{
    __shared__ ulonglong2 SWq[2][5][32];   // weights, duplicated pairs, 16B granules
    __shared__ ulonglong2 SBq[2][5][4];    // biases,  duplicated pairs, 16B granules

    const int tid = threadIdx.x;

    // weights: 320 ulonglong2 total
    for (int idx = tid; idx < 320; idx += 128) {
        int m = idx / 160, r = idx % 160, l = r / 32, k = r % 32;
        int j = k / 4, i2 = k % 4;
        const float* Wp = P.p[m * 10 + l];
        float w0 = Wp[j * 8 + i2 * 2], w1 = Wp[j * 8 + i2 * 2 + 1];
        SWq[m][l][k] = make_ulonglong2(pack2(w0, w0), pack2(w1, w1));
    }
    // biases: 40 ulonglong2 total
    for (int idx = tid; idx < 40; idx += 128) {
        int m = idx / 20, r = idx % 20, l = r / 4, k = r % 4;
        const float* Bp = P.p[m * 10 + 5 + l];
        float b0 = Bp[2 * k], b1 = Bp[2 * k + 1];
        SBq[m][l][k] = make_ulonglong2(pack2(b0, b0), pack2(b1, b1));
    }
    __syncthreads();

    const int lane = tid & 31;
    const int warp = tid >> 5;
    long long warpBase = ((long long)blockIdx.x * 4 + warp) * 128;
    if (warpBase >= batch) return;  // batch % 128 == 0 -> active warps are full

    // Each thread: 2 pairs = 4 rows. Pair p = (warpBase + 64p + lane, +32).
    int rA[2], rB[2];
    u64 zl[2][8], zr[2][8];
#pragma unroll
    for (int p = 0; p < 2; p++) {
        rA[p] = (int)warpBase + p * 64 + lane;
        rB[p] = rA[p] + 32;
        const float* pa = z + (long long)rA[p] * 16;
        const float* pb = z + (long long)rB[p] * 16;
        float4 a0 = ld4<IOW>(pa),     a1 = ld4<IOW>(pa + 4);
        float4 a2 = ld4<IOW>(pa + 8), a3 = ld4<IOW>(pa + 12);
        float4 b0 = ld4<IOW>(pb),     b1 = ld4<IOW>(pb + 4);
        float4 b2 = ld4<IOW>(pb + 8), b3 = ld4<IOW>(pb + 12);

        // left-half passthrough: store immediately
        float* oa = out + (long long)rA[p] * 16;
        float* ob = out + (long long)rB[p] * 16;
        st4<IOW>(oa, a0);     st4<IOW>(oa + 4, a1);
        st4<IOW>(ob, b0);     st4<IOW>(ob + 4, b1);

        zl[p][0] = pack2(a0.x, b0.x); zl[p][1] = pack2(a0.y, b0.y);
        zl[p][2] = pack2(a0.z, b0.z); zl[p][3] = pack2(a0.w, b0.w);
        zl[p][4] = pack2(a1.x, b1.x); zl[p][5] = pack2(a1.y, b1.y);
        zl[p][6] = pack2(a1.z, b1.z); zl[p][7] = pack2(a1.w, b1.w);

        zr[p][0] = pack2(a2.x, b2.x); zr[p][1] = pack2(a2.y, b2.y);
        zr[p][2] = pack2(a2.z, b2.z); zr[p][3] = pack2(a2.w, b2.w);
        zr[p][4] = pack2(a3.x, b3.x); zr[p][5] = pack2(a3.y, b3.y);
        zr[p][6] = pack2(a3.z, b3.z); zr[p][7] = pack2(a3.w, b3.w);
    }

    // Layer 0 of BOTH chains consumes zl, then zl is dead (limits reg pressure).
    u64 s[2][8], bb[2][8], t[2][8], ls[2][8], bv[2][8];
    layer2pairQ(SWq[0][0], SBq[0][0], zl[0], zl[1], s[0],  s[1],  true);
    layer2pairQ(SWq[1][0], SBq[1][0], zl[0], zl[1], bb[0], bb[1], true);

    // log_s chain
    layer2pairQ(SWq[0][1], SBq[0][1], s[0], s[1], t[0], t[1], true);
    layer2pairQ(SWq[0][2], SBq[0][2], t[0], t[1], s[0], s[1], true);
    layer2pairQ(SWq[0][3], SBq[0][3], s[0], s[1], t[0], t[1], true);
    layer2pairQ(SWq[0][4], SBq[0][4], t[0], t[1], ls[0], ls[1], false);

    // b chain
    layer2pairQ(SWq[1][1], SBq[1][1], bb[0], bb[1], t[0],  t[1],  true);
    layer2pairQ(SWq[1][2], SBq[1][2], t[0],  t[1],  bb[0], bb[1], true);
    layer2pairQ(SWq[1][3], SBq[1][3], bb[0], bb[1], t[0],  t[1],  true);
    layer2pairQ(SWq[1][4], SBq[1][4], t[0],  t[1],  bv[0], bv[1], false);

    // yr = exp(log_s) * zr + b
#pragma unroll
    for (int p = 0; p < 2; p++) {
        float yA[8], yB[8];
#pragma unroll
        for (int j = 0; j < 8; j++) {
            float lA, lB, bA, bB, zA, zB;
            unpack2(ls[p][j], lA, lB);
            unpack2(bv[p][j], bA, bB);
            unpack2(zr[p][j], zA, zB);
            yA[j] = fmaf(__expf(lA), zA, bA);
            yB[j] = fmaf(__expf(lB), zB, bB);
        }
        float* oa = out + (long long)rA[p] * 16 + 8;
        float* ob = out + (long long)rB[p] * 16 + 8;
        st4<IOW>(oa,     make_float4(yA[0], yA[1], yA[2], yA[3]));
        st4<IOW>(oa + 4, make_float4(yA[4], yA[5], yA[6], yA[7]));
        st4<IOW>(ob,     make_float4(yB[0], yB[1], yB[2], yB[3]));
        st4<IOW>(ob + 4, make_float4(yB[4], yB[5], yB[6], yB[7]));
    }
}

extern "C" void kernel_launch(void* const* d_in, const int* in_sizes, int n_in,
                              void* d_out, int out_size)
{
    // ---- locate z: the (unique) huge input ----
    int zi = 0;
    for (int i = 0; i < n_in; i++) {
        if (in_sizes[i] > in_sizes[zi]) zi = i;
    }
    const float* z = (const float*)d_in[zi];
    long long batchLL = (long long)in_sizes[zi] / 16;
    int batch = (int)batchLL;
    float* out = (float*)d_out;

    // ---- build the 20 layer-parameter pointers, layout-adaptively ----
    Params P;
    if (n_in >= 21) {
        int k = 0;
        for (int i = 0; i < n_in && k < 20; i++) {
            if (i == zi) continue;
            P.p[k++] = (const float*)d_in[i];
        }
    } else {
        int wslot = 0, bslot = 0;  // 0 -> logs, 1 -> b
        for (int i = 0; i < n_in; i++) {
            if (i == zi) continue;
            const float* base = (const float*)d_in[i];
            int sz = in_sizes[i];
            if (sz == 320) {            // stacked weights (5,8,8)
                int m = (wslot++ == 0) ? 0 : 1;
                for (int l = 0; l < 5; l++) P.p[m * 10 + l] = base + 64 * l;
            } else if (sz == 40) {      // stacked biases (5,8)
                int m = (bslot++ == 0) ? 0 : 1;
                for (int l = 0; l < 5; l++) P.p[m * 10 + 5 + l] = base + 8 * l;
            }
        }
    }

    int rowsPerBlock = 512;                // 128 threads * 4 rows
    int grid = (int)((batchLL + rowsPerBlock - 1) / rowsPerBlock);

    uintptr_t mis = (uintptr_t)z | (uintptr_t)out;
    if ((mis & 15) == 0) {
        affine_coupling_kernel<4><<<grid, 128>>>(z, out, batch, P);
    } else if ((mis & 7) == 0) {
        affine_coupling_kernel<2><<<grid, 128>>>(z, out, batch, P);
    } else {
        affine_coupling_kernel<1><<<grid, 128>>>(z, out, batch, P);
    }
}